// round 9
// baseline (speedup 1.0000x reference)
#include <cuda_runtime.h>
#include <cuda_bf16.h>
#include <math.h>
#include <cstdint>

#define CB 16
#define CS 1024
#define CD 1024
#define CH 16
#define CDK 64
#define CM (CB*CS)   /* 16384 rows */
#define QP 3072      /* fused qkv row pitch */

// =====================================================================
// helpers
// =====================================================================
__device__ __forceinline__ uint32_t smem_to_u32(const void* smem_ptr) {
    uint32_t addr;
    asm("{ .reg .u64 tmp; cvta.to.shared.u64 tmp, %1; cvt.u32.u64 %0, tmp; }"
        : "=r"(addr) : "l"(smem_ptr));
    return addr;
}
__device__ __forceinline__ void cpasync16(uint32_t dst, const void* src) {
    asm volatile("cp.async.cg.shared.global [%0], [%1], 16;\n" :: "r"(dst), "l"(src));
}
__device__ __forceinline__ void cp_commit() { asm volatile("cp.async.commit_group;" ::: "memory"); }
template<int N> __device__ __forceinline__ void cp_wait() {
    asm volatile("cp.async.wait_group %0;" :: "n"(N) : "memory");
}
__device__ __forceinline__ void ldx4(uint32_t r[4], uint32_t addr) {
    asm volatile("ldmatrix.sync.aligned.m8n8.x4.shared.b16 {%0,%1,%2,%3}, [%4];"
        : "=r"(r[0]), "=r"(r[1]), "=r"(r[2]), "=r"(r[3]) : "r"(addr));
}
__device__ __forceinline__ void ldx4t(uint32_t r[4], uint32_t addr) {
    asm volatile("ldmatrix.sync.aligned.m8n8.x4.trans.shared.b16 {%0,%1,%2,%3}, [%4];"
        : "=r"(r[0]), "=r"(r[1]), "=r"(r[2]), "=r"(r[3]) : "r"(addr));
}
__device__ __forceinline__ void mma16816(float c[4], const uint32_t a[4],
                                         uint32_t b0, uint32_t b1) {
    asm volatile(
        "mma.sync.aligned.m16n8k16.row.col.f32.bf16.bf16.f32 "
        "{%0,%1,%2,%3}, {%4,%5,%6,%7}, {%8,%9}, {%0,%1,%2,%3};"
        : "+f"(c[0]), "+f"(c[1]), "+f"(c[2]), "+f"(c[3])
        : "r"(a[0]), "r"(a[1]), "r"(a[2]), "r"(a[3]), "r"(b0), "r"(b1));
}
// pack (x,y) into bf16x2 hi-part + residual lo-part
__device__ __forceinline__ void split2(float x, float y, uint32_t& h, uint32_t& l) {
    uint32_t hp;
    asm("cvt.rn.bf16x2.f32 %0, %1, %2;" : "=r"(hp) : "f"(y), "f"(x));
    float fx = __uint_as_float(hp << 16);
    float fy = __uint_as_float(hp & 0xffff0000u);
    uint32_t lp;
    asm("cvt.rn.bf16x2.f32 %0, %1, %2;" : "=r"(lp) : "f"(y - fy), "f"(x - fx));
    h = hp; l = lp;
}
__device__ __forceinline__ float fexp2(float x) {
    float y; asm("ex2.approx.ftz.f32 %0, %1;" : "=f"(y) : "f"(x)); return y;
}

// ---------- scratch (device globals: allocation-free) ----------
__device__ __nv_bfloat16 g_xhi[(size_t)CM * CD];
__device__ __nv_bfloat16 g_xlo[(size_t)CM * CD];
__device__ __nv_bfloat16 g_qkvhi[(size_t)CM * QP];
__device__ __nv_bfloat16 g_qkvlo[(size_t)CM * QP];
__device__ __nv_bfloat16 g_chi[(size_t)CM * CD];
__device__ __nv_bfloat16 g_clo[(size_t)CM * CD];
__device__ __nv_bfloat16 g_wthi[(size_t)QP * CD];
__device__ __nv_bfloat16 g_wtlo[(size_t)QP * CD];

// =====================================================================
// fp32 -> split bf16 (hi + residual lo), vectorized
// =====================================================================
__global__ void split_kernel(const float4* __restrict__ x,
                             uint32_t* __restrict__ hi,
                             uint32_t* __restrict__ lo, int n4) {
    int i = blockIdx.x * blockDim.x + threadIdx.x;
    if (i >= n4) return;
    float4 v = x[i];
    uint32_t h0, l0, h1, l1;
    split2(v.x, v.y, h0, l0);
    split2(v.z, v.w, h1, l1);
    hi[2*i] = h0; hi[2*i+1] = h1;
    lo[2*i] = l0; lo[2*i+1] = l1;
}

// =====================================================================
// W[K,N] fp32 -> transposed split bf16 T[N,K] (hi, lo)
// =====================================================================
__global__ void tsplit_kernel(const float* __restrict__ W,
                              __nv_bfloat16* __restrict__ Thi,
                              __nv_bfloat16* __restrict__ Tlo) {
    __shared__ float t[32][33];
    int n0 = blockIdx.x * 32, k0 = blockIdx.y * 32;
    int tx = threadIdx.x, ty = threadIdx.y;   // 32 x 8
    #pragma unroll
    for (int j = 0; j < 4; ++j)
        t[ty + 8*j][tx] = W[(size_t)(k0 + ty + 8*j) * CD + n0 + tx];
    __syncthreads();
    #pragma unroll
    for (int j = 0; j < 4; ++j) {
        float v = t[tx][ty + 8*j];
        __nv_bfloat16 h = __float2bfloat16_rn(v);
        __nv_bfloat16 l = __float2bfloat16_rn(v - __bfloat162float(h));
        size_t o = (size_t)(n0 + ty + 8*j) * CD + k0 + tx;
        Thi[o] = h; Tlo[o] = l;
    }
}

// =====================================================================
// mma.sync bf16 split GEMM: C = Afp32 @ Bfp32 (3-term emulation)
// Block 128x128x32, 8 warps (2x4), warp tile 64x32.
// 4-stage cp.async pipeline, one __syncthreads per iteration.
// =====================================================================
#define ROWB 80
#define ASTG (128 * ROWB)
#define STG  (4 * ASTG)          /* 40960 B per stage */
#define GSMEM (4 * STG)          /* 163840 B */

__device__ __forceinline__ void gm_load_stage(
    uint32_t sb, int s,
    const __nv_bfloat16* __restrict__ Ahi, const __nv_bfloat16* __restrict__ Alo,
    const __nv_bfloat16* __restrict__ Bhi, const __nv_bfloat16* __restrict__ Blo,
    int tid, int m0, int n0, int k0)
{
    if (k0 < CD) {
        uint32_t base = sb + (uint32_t)s * STG;
        #pragma unroll
        for (int j = 0; j < 2; ++j) {
            int c = tid + j * 256;
            int row = c >> 2, kc = c & 3;
            uint32_t d = base + row * ROWB + kc * 16;
            size_t g = (size_t)(m0 + row) * CD + k0 + kc * 8;
            cpasync16(d, Ahi + g);
            cpasync16(d + ASTG, Alo + g);
        }
        #pragma unroll
        for (int j = 0; j < 2; ++j) {
            int c = tid + j * 256;
            int row = c >> 2, kc = c & 3;
            uint32_t d = base + 2 * ASTG + row * ROWB + kc * 16;
            size_t g = (size_t)(n0 + row) * CD + k0 + kc * 8;
            cpasync16(d, Bhi + g);
            cpasync16(d + ASTG, Blo + g);
        }
    }
    cp_commit();
}

template<bool SPLIT>
__global__ void __launch_bounds__(256, 1) gemm_mma_kernel(
    const __nv_bfloat16* __restrict__ Ahi, const __nv_bfloat16* __restrict__ Alo,
    const __nv_bfloat16* __restrict__ Bhi, const __nv_bfloat16* __restrict__ Blo,
    float* __restrict__ Cf,
    __nv_bfloat16* __restrict__ Chi, __nv_bfloat16* __restrict__ Clo,
    int NC)
{
    extern __shared__ __align__(128) char smem[];
    const uint32_t sb = smem_to_u32(smem);
    const int tid = threadIdx.x;
    const int lane = tid & 31, wid = tid >> 5;
    const int m0 = blockIdx.y * 128;
    const int n0 = blockIdx.x * 128;
    const int wm0 = (wid & 1) * 64;
    const int wn0 = (wid >> 1) * 32;

    float acc[4][4][4];
    #pragma unroll
    for (int i = 0; i < 4; ++i)
        #pragma unroll
        for (int j = 0; j < 4; ++j)
            #pragma unroll
            for (int q = 0; q < 4; ++q) acc[i][j][q] = 0.0f;

    gm_load_stage(sb, 0, Ahi, Alo, Bhi, Blo, tid, m0, n0, 0);
    gm_load_stage(sb, 1, Ahi, Alo, Bhi, Blo, tid, m0, n0, 32);
    gm_load_stage(sb, 2, Ahi, Alo, Bhi, Blo, tid, m0, n0, 64);

    const int lr = lane & 15;
    const int lc = (lane & 16) ? 16 : 0;

    for (int i = 0; i < 32; ++i) {
        cp_wait<2>();
        __syncthreads();
        // fill the slot freed by stage i-1 (barrier above guarantees all warps done)
        gm_load_stage(sb, (i + 3) & 3, Ahi, Alo, Bhi, Blo, tid, m0, n0, (i + 3) * 32);

        const uint32_t base = sb + (uint32_t)(i & 3) * STG;
        #pragma unroll
        for (int kk = 0; kk < 2; ++kk) {
            uint32_t afh[4][4], afl[4][4];
            uint32_t bh[4][2], bl[4][2];
            #pragma unroll
            for (int mi = 0; mi < 4; ++mi) {
                uint32_t ad = base + (wm0 + mi * 16 + lr) * ROWB + kk * 32 + lc;
                ldx4(afh[mi], ad);
                ldx4(afl[mi], ad + ASTG);
            }
            #pragma unroll
            for (int np = 0; np < 2; ++np) {
                uint32_t bd = base + 2 * ASTG + (wn0 + np * 16 + lr) * ROWB + kk * 32 + lc;
                uint32_t r[4];
                ldx4(r, bd);
                bh[np*2][0] = r[0]; bh[np*2][1] = r[2];
                bh[np*2+1][0] = r[1]; bh[np*2+1][1] = r[3];
                ldx4(r, bd + ASTG);
                bl[np*2][0] = r[0]; bl[np*2][1] = r[2];
                bl[np*2+1][0] = r[1]; bl[np*2+1][1] = r[3];
            }
            #pragma unroll
            for (int mi = 0; mi < 4; ++mi)
                #pragma unroll
                for (int ni = 0; ni < 4; ++ni) {
                    mma16816(acc[mi][ni], afh[mi], bh[ni][0], bh[ni][1]);
                    mma16816(acc[mi][ni], afh[mi], bl[ni][0], bl[ni][1]);
                    mma16816(acc[mi][ni], afl[mi], bh[ni][0], bh[ni][1]);
                }
        }
    }

    #pragma unroll
    for (int mi = 0; mi < 4; ++mi) {
        #pragma unroll
        for (int ni = 0; ni < 4; ++ni) {
            int r0 = m0 + wm0 + mi * 16 + (lane >> 2);
            int c0 = n0 + wn0 + ni * 8 + (lane & 3) * 2;
            if (!SPLIT) {
                *(float2*)&Cf[(size_t)r0 * NC + c0] = make_float2(acc[mi][ni][0], acc[mi][ni][1]);
                *(float2*)&Cf[(size_t)(r0 + 8) * NC + c0] = make_float2(acc[mi][ni][2], acc[mi][ni][3]);
            } else {
                uint32_t h, l;
                split2(acc[mi][ni][0], acc[mi][ni][1], h, l);
                *(uint32_t*)&Chi[(size_t)r0 * NC + c0] = h;
                *(uint32_t*)&Clo[(size_t)r0 * NC + c0] = l;
                split2(acc[mi][ni][2], acc[mi][ni][3], h, l);
                *(uint32_t*)&Chi[(size_t)(r0 + 8) * NC + c0] = h;
                *(uint32_t*)&Clo[(size_t)(r0 + 8) * NC + c0] = l;
            }
        }
    }
}

// =====================================================================
// Tensor-core flash attention (split bf16, 3-term):
// one CTA per (128-query tile, head, batch); 8 warps x 16 q rows.
// 3-stage KV pipeline, one sync/iter, Q fragments hoisted to registers.
// Reads fused QKV layout [B*S, 3072] (q:0..1023, k:1024..2047, v:2048..3071).
// =====================================================================
#define FPB 144                   /* smem pitch bytes (72 bf16) */
#define FTB (64 * FPB)            /* 9216 B per 64-row tile */
#define QTB (128 * FPB)           /* 18432 B per 128-row Q tile */
#define FNS 3
#define FL_SMEM (2*QTB + FNS*4*FTB)   /* 147456 B */
#define LOG2E 1.4426950408889634f

__global__ void __launch_bounds__(256, 1) flasht_kernel(
    const __nv_bfloat16* __restrict__ QKVhi, const __nv_bfloat16* __restrict__ QKVlo,
    const float* __restrict__ bias, const float* __restrict__ btr,
    __nv_bfloat16* __restrict__ Chi, __nv_bfloat16* __restrict__ Clo)
{
    extern __shared__ __align__(128) char smem[];
    const uint32_t sb = smem_to_u32(smem);
    const uint32_t sQh = sb;
    const uint32_t sKV = sb + 2 * QTB;

    const int tid = threadIdx.x, lane = tid & 31, wid = tid >> 5;
    const int h = blockIdx.y, b = blockIdx.z;
    const int q0 = blockIdx.x * 128;
    const int wq0 = wid * 16;
    const float bscale = btr[h] * LOG2E;
    const float sfac = 0.125f * LOG2E;

    const size_t bh_off = (size_t)b * CS * QP + (size_t)h * CDK;
    const __nv_bfloat16* Qgh = QKVhi + bh_off + (size_t)q0 * QP;
    const __nv_bfloat16* Qgl = QKVlo + bh_off + (size_t)q0 * QP;
    const __nv_bfloat16* Kgh = QKVhi + bh_off + 1024;
    const __nv_bfloat16* Kgl = QKVlo + bh_off + 1024;
    const __nv_bfloat16* Vgh = QKVhi + bh_off + 2048;
    const __nv_bfloat16* Vgl = QKVlo + bh_off + 2048;

    // ---- Q tile load (group 0) ----
    #pragma unroll
    for (int j = 0; j < 4; ++j) {
        int ch = tid + j * 256;          // 0..1023
        int row = ch >> 3, c = ch & 7;
        size_t g = (size_t)row * QP + c * 8;
        uint32_t d = sQh + row * FPB + c * 16;
        cpasync16(d, Qgh + g);
        cpasync16(d + QTB, Qgl + g);
    }
    cp_commit();

    // ---- KV stage loader (always commits; empty past the end) ----
    auto kv_load = [&](int slot, int kv0) {
        if (kv0 < CS) {
            uint32_t stg = sKV + (uint32_t)slot * 4 * FTB;
            #pragma unroll
            for (int j = 0; j < 2; ++j) {
                int ch = tid + j * 256;       // 0..511
                int row = ch >> 3, c = ch & 7;
                size_t g = (size_t)(kv0 + row) * QP + c * 8;
                uint32_t d = stg + row * FPB + c * 16;
                cpasync16(d,           Kgh + g);
                cpasync16(d + FTB,     Kgl + g);
                cpasync16(d + 2*FTB,   Vgh + g);
                cpasync16(d + 3*FTB,   Vgl + g);
            }
        }
        cp_commit();
    };
    kv_load(0, 0);
    kv_load(1, 64);

    const int lr = lane & 15;
    const uint32_t lc = (lane & 16) ? 16u : 0u;
    const int rl = lane >> 2;

    uint32_t qh[4][4], ql[4][4];   // Q fragments held in registers (loaded at it==0)

    float o[8][4];
    #pragma unroll
    for (int n = 0; n < 8; ++n)
        #pragma unroll
        for (int q = 0; q < 4; ++q) o[n][q] = 0.0f;
    float m_lo = -3.0e38f, m_hi = -3.0e38f, l_lo = 0.0f, l_hi = 0.0f;

    const float* b_lo = bias + (size_t)(q0 + wq0 + rl) * CS + 2 * (lane & 3);
    const float* b_hi = b_lo + 8 * CS;

    for (int it = 0; it < 16; ++it) {
        cp_wait<1>();
        __syncthreads();
        kv_load((it + 2) % FNS, (it + 2) * 64);

        if (it == 0) {
            #pragma unroll
            for (int kk = 0; kk < 4; ++kk) {
                uint32_t qad = sQh + (wq0 + lr) * FPB + kk * 32 + lc;
                ldx4(qh[kk], qad);
                ldx4(ql[kk], qad + QTB);
            }
        }

        const uint32_t stg = sKV + (uint32_t)(it % FNS) * 4 * FTB;
        const int kv0 = it * 64;

        // ---- scores: S = Q K^T (split 3-term) ----
        float sf[8][4];
        #pragma unroll
        for (int n = 0; n < 8; ++n)
            #pragma unroll
            for (int q = 0; q < 4; ++q) sf[n][q] = 0.0f;

        #pragma unroll
        for (int kk = 0; kk < 4; ++kk) {
            #pragma unroll
            for (int np = 0; np < 4; ++np) {
                uint32_t kad = stg + (np * 16 + lr) * FPB + kk * 32 + lc;
                uint32_t kh[4], kl[4];
                ldx4(kh, kad);
                ldx4(kl, kad + FTB);
                mma16816(sf[2*np],   qh[kk], kh[0], kh[2]);
                mma16816(sf[2*np],   qh[kk], kl[0], kl[2]);
                mma16816(sf[2*np],   ql[kk], kh[0], kh[2]);
                mma16816(sf[2*np+1], qh[kk], kh[1], kh[3]);
                mma16816(sf[2*np+1], qh[kk], kl[1], kl[3]);
                mma16816(sf[2*np+1], ql[kk], kh[1], kh[3]);
            }
        }

        // ---- bias + online softmax (base-2 domain) ----
        float mx_lo = -3.0e38f, mx_hi = -3.0e38f;
        #pragma unroll
        for (int n = 0; n < 8; ++n) {
            float2 bl = *(const float2*)(b_lo + kv0 + 8 * n);
            float2 bh2 = *(const float2*)(b_hi + kv0 + 8 * n);
            sf[n][0] = fmaf(sf[n][0], sfac, bscale * bl.x);
            sf[n][1] = fmaf(sf[n][1], sfac, bscale * bl.y);
            sf[n][2] = fmaf(sf[n][2], sfac, bscale * bh2.x);
            sf[n][3] = fmaf(sf[n][3], sfac, bscale * bh2.y);
            mx_lo = fmaxf(mx_lo, fmaxf(sf[n][0], sf[n][1]));
            mx_hi = fmaxf(mx_hi, fmaxf(sf[n][2], sf[n][3]));
        }
        mx_lo = fmaxf(mx_lo, __shfl_xor_sync(0xffffffffu, mx_lo, 1));
        mx_lo = fmaxf(mx_lo, __shfl_xor_sync(0xffffffffu, mx_lo, 2));
        mx_hi = fmaxf(mx_hi, __shfl_xor_sync(0xffffffffu, mx_hi, 1));
        mx_hi = fmaxf(mx_hi, __shfl_xor_sync(0xffffffffu, mx_hi, 2));

        float mn_lo = fmaxf(m_lo, mx_lo), mn_hi = fmaxf(m_hi, mx_hi);
        float al_lo = fexp2(m_lo - mn_lo), al_hi = fexp2(m_hi - mn_hi);
        m_lo = mn_lo; m_hi = mn_hi;

        float rs_lo = 0.0f, rs_hi = 0.0f;
        #pragma unroll
        for (int n = 0; n < 8; ++n) {
            sf[n][0] = fexp2(sf[n][0] - mn_lo);
            sf[n][1] = fexp2(sf[n][1] - mn_lo);
            sf[n][2] = fexp2(sf[n][2] - mn_hi);
            sf[n][3] = fexp2(sf[n][3] - mn_hi);
            rs_lo += sf[n][0] + sf[n][1];
            rs_hi += sf[n][2] + sf[n][3];
        }
        rs_lo += __shfl_xor_sync(0xffffffffu, rs_lo, 1);
        rs_lo += __shfl_xor_sync(0xffffffffu, rs_lo, 2);
        rs_hi += __shfl_xor_sync(0xffffffffu, rs_hi, 1);
        rs_hi += __shfl_xor_sync(0xffffffffu, rs_hi, 2);
        l_lo = l_lo * al_lo + rs_lo;
        l_hi = l_hi * al_hi + rs_hi;

        #pragma unroll
        for (int n = 0; n < 8; ++n) {
            o[n][0] *= al_lo; o[n][1] *= al_lo;
            o[n][2] *= al_hi; o[n][3] *= al_hi;
        }

        // ---- O += P V (P split in registers, V split in smem) ----
        #pragma unroll
        for (int ks = 0; ks < 4; ++ks) {
            uint32_t ph[4], pl[4];
            split2(sf[2*ks][0],   sf[2*ks][1],   ph[0], pl[0]);
            split2(sf[2*ks][2],   sf[2*ks][3],   ph[1], pl[1]);
            split2(sf[2*ks+1][0], sf[2*ks+1][1], ph[2], pl[2]);
            split2(sf[2*ks+1][2], sf[2*ks+1][3], ph[3], pl[3]);
            #pragma unroll
            for (int db = 0; db < 4; ++db) {
                uint32_t vad = stg + 2*FTB + (ks * 16 + lr) * FPB + db * 32 + lc;
                uint32_t vh[4], vl[4];
                ldx4t(vh, vad);
                ldx4t(vl, vad + FTB);
                mma16816(o[2*db],   ph, vh[0], vh[1]);
                mma16816(o[2*db],   ph, vl[0], vl[1]);
                mma16816(o[2*db],   pl, vh[0], vh[1]);
                mma16816(o[2*db+1], ph, vh[2], vh[3]);
                mma16816(o[2*db+1], ph, vl[2], vl[3]);
                mma16816(o[2*db+1], pl, vh[2], vh[3]);
            }
        }
    }

    // ---- normalize + write split bf16 ctx ----
    const float il = 1.0f / l_lo, ih = 1.0f / l_hi;
    const int gq = q0 + wq0 + rl;
    const size_t row_lo = ((size_t)b * CS + gq) * CD + (size_t)h * CDK + 2 * (lane & 3);
    const size_t row_hi = row_lo + (size_t)8 * CD;
    #pragma unroll
    for (int n = 0; n < 8; ++n) {
        uint32_t hh, ll;
        split2(o[n][0] * il, o[n][1] * il, hh, ll);
        *(uint32_t*)&Chi[row_lo + 8 * n] = hh;
        *(uint32_t*)&Clo[row_lo + 8 * n] = ll;
        split2(o[n][2] * ih, o[n][3] * ih, hh, ll);
        *(uint32_t*)&Chi[row_hi + 8 * n] = hh;
        *(uint32_t*)&Clo[row_hi + 8 * n] = ll;
    }
}

// =====================================================================
// launch
// =====================================================================
extern "C" void kernel_launch(void* const* d_in, const int* in_sizes, int n_in,
                              void* d_out, int out_size) {
    (void)in_sizes; (void)n_in; (void)out_size;
    const float* X   = (const float*)d_in[0];
    const float* bLL = (const float*)d_in[1];
    const float* Wq  = (const float*)d_in[2];
    const float* Wk  = (const float*)d_in[3];
    const float* Wv  = (const float*)d_in[4];
    const float* Wo  = (const float*)d_in[5];
    const float* btr = (const float*)d_in[6];
    float* out = (float*)d_out;

    __nv_bfloat16 *xhi, *xlo, *qkvhi, *qkvlo, *chi, *clo, *wthi, *wtlo;
    cudaGetSymbolAddress((void**)&xhi,   g_xhi);
    cudaGetSymbolAddress((void**)&xlo,   g_xlo);
    cudaGetSymbolAddress((void**)&qkvhi, g_qkvhi);
    cudaGetSymbolAddress((void**)&qkvlo, g_qkvlo);
    cudaGetSymbolAddress((void**)&chi,   g_chi);
    cudaGetSymbolAddress((void**)&clo,   g_clo);
    cudaGetSymbolAddress((void**)&wthi,  g_wthi);
    cudaGetSymbolAddress((void**)&wtlo,  g_wtlo);

    cudaFuncSetAttribute(gemm_mma_kernel<true>,  cudaFuncAttributeMaxDynamicSharedMemorySize, GSMEM);
    cudaFuncSetAttribute(gemm_mma_kernel<false>, cudaFuncAttributeMaxDynamicSharedMemorySize, GSMEM);
    cudaFuncSetAttribute(flasht_kernel, cudaFuncAttributeMaxDynamicSharedMemorySize, FL_SMEM);

    const int n4x = (CM * CD) / 4;
    const dim3 tsg(32, 32), tsb(32, 8);

    // X -> split bf16
    split_kernel<<<(n4x + 255) / 256, 256>>>((const float4*)X,
        (uint32_t*)xhi, (uint32_t*)xlo, n4x);

    // fused weight transpose: Wt rows [0,1024)=Wq^T, [1024,2048)=Wk^T, [2048,3072)=Wv^T
    tsplit_kernel<<<tsg, tsb>>>(Wq, wthi,                          wtlo);
    tsplit_kernel<<<tsg, tsb>>>(Wk, wthi + (size_t)1024 * CD,      wtlo + (size_t)1024 * CD);
    tsplit_kernel<<<tsg, tsb>>>(Wv, wthi + (size_t)2048 * CD,      wtlo + (size_t)2048 * CD);

    // fused QKV projection: [CM, 3072] split bf16 output
    gemm_mma_kernel<true><<<dim3(QP / 128, CM / 128), 256, GSMEM>>>(
        xhi, xlo, wthi, wtlo, nullptr, qkvhi, qkvlo, QP);

    // attention (tensor-core flash) -> split bf16 ctx
    flasht_kernel<<<dim3(CS / 128, CH, CB), 256, FL_SMEM>>>(
        qkvhi, qkvlo, bLL, btr, chi, clo);

    // output projection -> fp32 out
    tsplit_kernel<<<tsg, tsb>>>(Wo, wthi, wtlo);
    gemm_mma_kernel<false><<<dim3(CD / 128, CM / 128), 256, GSMEM>>>(
        chi, clo, wthi, wtlo, out, nullptr, nullptr, CD);
}

// round 10
// speedup vs baseline: 1.0237x; 1.0237x over previous
#include <cuda_runtime.h>
#include <cuda_bf16.h>
#include <math.h>
#include <cstdint>

#define CB 16
#define CS 1024
#define CD 1024
#define CH 16
#define CDK 64
#define CM (CB*CS)   /* 16384 rows */
#define QP 3072      /* fused qkv row pitch */

// =====================================================================
// helpers
// =====================================================================
__device__ __forceinline__ uint32_t smem_to_u32(const void* smem_ptr) {
    uint32_t addr;
    asm("{ .reg .u64 tmp; cvta.to.shared.u64 tmp, %1; cvt.u32.u64 %0, tmp; }"
        : "=r"(addr) : "l"(smem_ptr));
    return addr;
}
__device__ __forceinline__ void cpasync16(uint32_t dst, const void* src) {
    asm volatile("cp.async.cg.shared.global [%0], [%1], 16;\n" :: "r"(dst), "l"(src));
}
__device__ __forceinline__ void cp_commit() { asm volatile("cp.async.commit_group;" ::: "memory"); }
template<int N> __device__ __forceinline__ void cp_wait() {
    asm volatile("cp.async.wait_group %0;" :: "n"(N) : "memory");
}
__device__ __forceinline__ void ldx4(uint32_t r[4], uint32_t addr) {
    asm volatile("ldmatrix.sync.aligned.m8n8.x4.shared.b16 {%0,%1,%2,%3}, [%4];"
        : "=r"(r[0]), "=r"(r[1]), "=r"(r[2]), "=r"(r[3]) : "r"(addr));
}
__device__ __forceinline__ void ldx4t(uint32_t r[4], uint32_t addr) {
    asm volatile("ldmatrix.sync.aligned.m8n8.x4.trans.shared.b16 {%0,%1,%2,%3}, [%4];"
        : "=r"(r[0]), "=r"(r[1]), "=r"(r[2]), "=r"(r[3]) : "r"(addr));
}
__device__ __forceinline__ void mma16816(float c[4], const uint32_t a[4],
                                         uint32_t b0, uint32_t b1) {
    asm volatile(
        "mma.sync.aligned.m16n8k16.row.col.f32.bf16.bf16.f32 "
        "{%0,%1,%2,%3}, {%4,%5,%6,%7}, {%8,%9}, {%0,%1,%2,%3};"
        : "+f"(c[0]), "+f"(c[1]), "+f"(c[2]), "+f"(c[3])
        : "r"(a[0]), "r"(a[1]), "r"(a[2]), "r"(a[3]), "r"(b0), "r"(b1));
}
// pack (x,y) into bf16x2 hi-part + residual lo-part
__device__ __forceinline__ void split2(float x, float y, uint32_t& h, uint32_t& l) {
    uint32_t hp;
    asm("cvt.rn.bf16x2.f32 %0, %1, %2;" : "=r"(hp) : "f"(y), "f"(x));
    float fx = __uint_as_float(hp << 16);
    float fy = __uint_as_float(hp & 0xffff0000u);
    uint32_t lp;
    asm("cvt.rn.bf16x2.f32 %0, %1, %2;" : "=r"(lp) : "f"(y - fy), "f"(x - fx));
    h = hp; l = lp;
}
__device__ __forceinline__ float fexp2(float x) {
    float y; asm("ex2.approx.ftz.f32 %0, %1;" : "=f"(y) : "f"(x)); return y;
}

// ---------- scratch (device globals: allocation-free) ----------
__device__ __nv_bfloat16 g_xhi[(size_t)CM * CD];
__device__ __nv_bfloat16 g_xlo[(size_t)CM * CD];
__device__ __nv_bfloat16 g_qkvhi[(size_t)CM * QP];
__device__ __nv_bfloat16 g_qkvlo[(size_t)CM * QP];
__device__ __nv_bfloat16 g_chi[(size_t)CM * CD];
__device__ __nv_bfloat16 g_clo[(size_t)CM * CD];
__device__ __nv_bfloat16 g_wthi[(size_t)QP * CD];
__device__ __nv_bfloat16 g_wtlo[(size_t)QP * CD];

// =====================================================================
// fp32 -> split bf16 (hi + residual lo), vectorized
// =====================================================================
__global__ void split_kernel(const float4* __restrict__ x,
                             uint32_t* __restrict__ hi,
                             uint32_t* __restrict__ lo, int n4) {
    int i = blockIdx.x * blockDim.x + threadIdx.x;
    if (i >= n4) return;
    float4 v = x[i];
    uint32_t h0, l0, h1, l1;
    split2(v.x, v.y, h0, l0);
    split2(v.z, v.w, h1, l1);
    hi[2*i] = h0; hi[2*i+1] = h1;
    lo[2*i] = l0; lo[2*i+1] = l1;
}

// =====================================================================
// W[K,N] fp32 -> transposed split bf16 T[N,K] (hi, lo)
// =====================================================================
__global__ void tsplit_kernel(const float* __restrict__ W,
                              __nv_bfloat16* __restrict__ Thi,
                              __nv_bfloat16* __restrict__ Tlo) {
    __shared__ float t[32][33];
    int n0 = blockIdx.x * 32, k0 = blockIdx.y * 32;
    int tx = threadIdx.x, ty = threadIdx.y;   // 32 x 8
    #pragma unroll
    for (int j = 0; j < 4; ++j)
        t[ty + 8*j][tx] = W[(size_t)(k0 + ty + 8*j) * CD + n0 + tx];
    __syncthreads();
    #pragma unroll
    for (int j = 0; j < 4; ++j) {
        float v = t[tx][ty + 8*j];
        __nv_bfloat16 h = __float2bfloat16_rn(v);
        __nv_bfloat16 l = __float2bfloat16_rn(v - __bfloat162float(h));
        size_t o = (size_t)(n0 + ty + 8*j) * CD + k0 + tx;
        Thi[o] = h; Tlo[o] = l;
    }
}

// =====================================================================
// mma.sync bf16 split GEMM: C = Afp32 @ Bfp32 (3-term emulation)
// Block 128x256x32, 8 warps (2x4), warp tile 64x64.
// 3-stage cp.async pipeline, single __syncthreads per iteration.
// =====================================================================
#define ROWB 80
#define AST (128 * ROWB)          /* 10240 */
#define BST (256 * ROWB)          /* 20480 */
#define STG (2*AST + 2*BST)       /* 61440 per stage */
#define NSTG 3
#define GSMEM (NSTG * STG)        /* 184320 B */

__device__ __forceinline__ void gm_load_stage(
    uint32_t sb, int s,
    const __nv_bfloat16* __restrict__ Ahi, const __nv_bfloat16* __restrict__ Alo,
    const __nv_bfloat16* __restrict__ Bhi, const __nv_bfloat16* __restrict__ Blo,
    int tid, int m0, int n0, int k0)
{
    if (k0 < CD) {
        uint32_t base = sb + (uint32_t)s * STG;
        #pragma unroll
        for (int j = 0; j < 2; ++j) {
            int c = tid + j * 256;            // 0..511
            int row = c >> 2, kc = c & 3;
            uint32_t d = base + row * ROWB + kc * 16;
            size_t g = (size_t)(m0 + row) * CD + k0 + kc * 8;
            cpasync16(d, Ahi + g);
            cpasync16(d + AST, Alo + g);
        }
        #pragma unroll
        for (int j = 0; j < 4; ++j) {
            int c = tid + j * 256;            // 0..1023
            int row = c >> 2, kc = c & 3;
            uint32_t d = base + 2 * AST + row * ROWB + kc * 16;
            size_t g = (size_t)(n0 + row) * CD + k0 + kc * 8;
            cpasync16(d, Bhi + g);
            cpasync16(d + BST, Blo + g);
        }
    }
    cp_commit();
}

template<bool SPLIT>
__global__ void __launch_bounds__(256, 1) gemm_mma_kernel(
    const __nv_bfloat16* __restrict__ Ahi, const __nv_bfloat16* __restrict__ Alo,
    const __nv_bfloat16* __restrict__ Bhi, const __nv_bfloat16* __restrict__ Blo,
    float* __restrict__ Cf,
    __nv_bfloat16* __restrict__ Chi, __nv_bfloat16* __restrict__ Clo,
    int NC)
{
    extern __shared__ __align__(128) char smem[];
    const uint32_t sb = smem_to_u32(smem);
    const int tid = threadIdx.x;
    const int lane = tid & 31, wid = tid >> 5;
    const int m0 = blockIdx.y * 128;
    const int n0 = blockIdx.x * 256;
    const int wm0 = (wid & 1) * 64;
    const int wn0 = (wid >> 1) * 64;

    float acc[4][8][4];
    #pragma unroll
    for (int i = 0; i < 4; ++i)
        #pragma unroll
        for (int j = 0; j < 8; ++j)
            #pragma unroll
            for (int q = 0; q < 4; ++q) acc[i][j][q] = 0.0f;

    gm_load_stage(sb, 0, Ahi, Alo, Bhi, Blo, tid, m0, n0, 0);
    gm_load_stage(sb, 1, Ahi, Alo, Bhi, Blo, tid, m0, n0, 32);

    const int lr = lane & 15;
    const int lc = (lane & 16) ? 16 : 0;

    int slot_ld = 2, slot_cp = 0;
    for (int i = 0; i < 32; ++i) {
        cp_wait<1>();
        __syncthreads();
        gm_load_stage(sb, slot_ld, Ahi, Alo, Bhi, Blo, tid, m0, n0, (i + 2) * 32);
        if (++slot_ld == NSTG) slot_ld = 0;

        const uint32_t base = sb + (uint32_t)slot_cp * STG;
        if (++slot_cp == NSTG) slot_cp = 0;

        #pragma unroll
        for (int kk = 0; kk < 2; ++kk) {
            uint32_t afh[4][4], afl[4][4];
            uint32_t bh[8][2], bl[8][2];
            #pragma unroll
            for (int mi = 0; mi < 4; ++mi) {
                uint32_t ad = base + (wm0 + mi * 16 + lr) * ROWB + kk * 32 + lc;
                ldx4(afh[mi], ad);
                ldx4(afl[mi], ad + AST);
            }
            #pragma unroll
            for (int np = 0; np < 4; ++np) {
                uint32_t bd = base + 2 * AST + (wn0 + np * 16 + lr) * ROWB + kk * 32 + lc;
                uint32_t r[4];
                ldx4(r, bd);
                bh[np*2][0] = r[0]; bh[np*2][1] = r[2];
                bh[np*2+1][0] = r[1]; bh[np*2+1][1] = r[3];
                ldx4(r, bd + BST);
                bl[np*2][0] = r[0]; bl[np*2][1] = r[2];
                bl[np*2+1][0] = r[1]; bl[np*2+1][1] = r[3];
            }
            #pragma unroll
            for (int mi = 0; mi < 4; ++mi)
                #pragma unroll
                for (int ni = 0; ni < 8; ++ni) {
                    mma16816(acc[mi][ni], afh[mi], bh[ni][0], bh[ni][1]);
                    mma16816(acc[mi][ni], afh[mi], bl[ni][0], bl[ni][1]);
                    mma16816(acc[mi][ni], afl[mi], bh[ni][0], bh[ni][1]);
                }
        }
    }

    #pragma unroll
    for (int mi = 0; mi < 4; ++mi) {
        #pragma unroll
        for (int ni = 0; ni < 8; ++ni) {
            int r0 = m0 + wm0 + mi * 16 + (lane >> 2);
            int c0 = n0 + wn0 + ni * 8 + (lane & 3) * 2;
            if (!SPLIT) {
                *(float2*)&Cf[(size_t)r0 * NC + c0] = make_float2(acc[mi][ni][0], acc[mi][ni][1]);
                *(float2*)&Cf[(size_t)(r0 + 8) * NC + c0] = make_float2(acc[mi][ni][2], acc[mi][ni][3]);
            } else {
                uint32_t h, l;
                split2(acc[mi][ni][0], acc[mi][ni][1], h, l);
                *(uint32_t*)&Chi[(size_t)r0 * NC + c0] = h;
                *(uint32_t*)&Clo[(size_t)r0 * NC + c0] = l;
                split2(acc[mi][ni][2], acc[mi][ni][3], h, l);
                *(uint32_t*)&Chi[(size_t)(r0 + 8) * NC + c0] = h;
                *(uint32_t*)&Clo[(size_t)(r0 + 8) * NC + c0] = l;
            }
        }
    }
}

// =====================================================================
// Tensor-core flash attention (split bf16, 3-term):
// one CTA per (128-query tile, head, batch); 8 warps x 16 q rows.
// 2-stage KV pipeline (occupancy 2), Q fragments hoisted to registers.
// Reads fused QKV layout [B*S, 3072]; writes split bf16 ctx.
// =====================================================================
#define FPB 144                   /* smem pitch bytes (72 bf16) */
#define FTB (64 * FPB)            /* 9216 B per 64-row tile */
#define QTB (128 * FPB)           /* 18432 B per 128-row Q tile */
#define FL_SMEM (2*QTB + 2*4*FTB) /* 110592 B -> 2 CTAs/SM */
#define LOG2E 1.4426950408889634f

__global__ void __launch_bounds__(256, 2) flasht_kernel(
    const __nv_bfloat16* __restrict__ QKVhi, const __nv_bfloat16* __restrict__ QKVlo,
    const float* __restrict__ bias, const float* __restrict__ btr,
    __nv_bfloat16* __restrict__ Chi, __nv_bfloat16* __restrict__ Clo)
{
    extern __shared__ __align__(128) char smem[];
    const uint32_t sb = smem_to_u32(smem);
    const uint32_t sQh = sb;
    const uint32_t sKV = sb + 2 * QTB;

    const int tid = threadIdx.x, lane = tid & 31, wid = tid >> 5;
    const int h = blockIdx.y, b = blockIdx.z;
    const int q0 = blockIdx.x * 128;
    const int wq0 = wid * 16;
    const float bscale = btr[h] * LOG2E;
    const float sfac = 0.125f * LOG2E;

    const size_t bh_off = (size_t)b * CS * QP + (size_t)h * CDK;
    const __nv_bfloat16* Qgh = QKVhi + bh_off + (size_t)q0 * QP;
    const __nv_bfloat16* Qgl = QKVlo + bh_off + (size_t)q0 * QP;
    const __nv_bfloat16* Kgh = QKVhi + bh_off + 1024;
    const __nv_bfloat16* Kgl = QKVlo + bh_off + 1024;
    const __nv_bfloat16* Vgh = QKVhi + bh_off + 2048;
    const __nv_bfloat16* Vgl = QKVlo + bh_off + 2048;

    // ---- Q tile load (group 0) ----
    #pragma unroll
    for (int j = 0; j < 4; ++j) {
        int ch = tid + j * 256;          // 0..1023
        int row = ch >> 3, c = ch & 7;
        size_t g = (size_t)row * QP + c * 8;
        uint32_t d = sQh + row * FPB + c * 16;
        cpasync16(d, Qgh + g);
        cpasync16(d + QTB, Qgl + g);
    }
    cp_commit();

    // ---- KV stage loader (always commits; empty past the end) ----
    auto kv_load = [&](int slot, int kv0) {
        if (kv0 < CS) {
            uint32_t stg = sKV + (uint32_t)slot * 4 * FTB;
            #pragma unroll
            for (int j = 0; j < 2; ++j) {
                int ch = tid + j * 256;       // 0..511
                int row = ch >> 3, c = ch & 7;
                size_t g = (size_t)(kv0 + row) * QP + c * 8;
                uint32_t d = stg + row * FPB + c * 16;
                cpasync16(d,           Kgh + g);
                cpasync16(d + FTB,     Kgl + g);
                cpasync16(d + 2*FTB,   Vgh + g);
                cpasync16(d + 3*FTB,   Vgl + g);
            }
        }
        cp_commit();
    };
    kv_load(0, 0);
    kv_load(1, 64);

    const int lr = lane & 15;
    const uint32_t lc = (lane & 16) ? 16u : 0u;
    const int rl = lane >> 2;

    uint32_t qh[4][4], ql[4][4];   // Q fragments in registers (loaded at it==0)

    float o[8][4];
    #pragma unroll
    for (int n = 0; n < 8; ++n)
        #pragma unroll
        for (int q = 0; q < 4; ++q) o[n][q] = 0.0f;
    float m_lo = -3.0e38f, m_hi = -3.0e38f, l_lo = 0.0f, l_hi = 0.0f;

    const float* b_lo = bias + (size_t)(q0 + wq0 + rl) * CS + 2 * (lane & 3);
    const float* b_hi = b_lo + 8 * CS;

    for (int it = 0; it < 16; ++it) {
        const int s = it & 1;
        cp_wait<1>();
        __syncthreads();

        if (it == 0) {
            #pragma unroll
            for (int kk = 0; kk < 4; ++kk) {
                uint32_t qad = sQh + (wq0 + lr) * FPB + kk * 32 + lc;
                ldx4(qh[kk], qad);
                ldx4(ql[kk], qad + QTB);
            }
        }

        const uint32_t stg = sKV + (uint32_t)s * 4 * FTB;
        const int kv0 = it * 64;

        // ---- scores: S = Q K^T (split 3-term) ----
        float sf[8][4];
        #pragma unroll
        for (int n = 0; n < 8; ++n)
            #pragma unroll
            for (int q = 0; q < 4; ++q) sf[n][q] = 0.0f;

        #pragma unroll
        for (int kk = 0; kk < 4; ++kk) {
            #pragma unroll
            for (int np = 0; np < 4; ++np) {
                uint32_t kad = stg + (np * 16 + lr) * FPB + kk * 32 + lc;
                uint32_t kh[4], kl[4];
                ldx4(kh, kad);
                ldx4(kl, kad + FTB);
                mma16816(sf[2*np],   qh[kk], kh[0], kh[2]);
                mma16816(sf[2*np],   qh[kk], kl[0], kl[2]);
                mma16816(sf[2*np],   ql[kk], kh[0], kh[2]);
                mma16816(sf[2*np+1], qh[kk], kh[1], kh[3]);
                mma16816(sf[2*np+1], qh[kk], kl[1], kl[3]);
                mma16816(sf[2*np+1], ql[kk], kh[1], kh[3]);
            }
        }

        // ---- bias + online softmax (base-2 domain) ----
        float mx_lo = -3.0e38f, mx_hi = -3.0e38f;
        #pragma unroll
        for (int n = 0; n < 8; ++n) {
            float2 bl = *(const float2*)(b_lo + kv0 + 8 * n);
            float2 bh2 = *(const float2*)(b_hi + kv0 + 8 * n);
            sf[n][0] = fmaf(sf[n][0], sfac, bscale * bl.x);
            sf[n][1] = fmaf(sf[n][1], sfac, bscale * bl.y);
            sf[n][2] = fmaf(sf[n][2], sfac, bscale * bh2.x);
            sf[n][3] = fmaf(sf[n][3], sfac, bscale * bh2.y);
            mx_lo = fmaxf(mx_lo, fmaxf(sf[n][0], sf[n][1]));
            mx_hi = fmaxf(mx_hi, fmaxf(sf[n][2], sf[n][3]));
        }
        mx_lo = fmaxf(mx_lo, __shfl_xor_sync(0xffffffffu, mx_lo, 1));
        mx_lo = fmaxf(mx_lo, __shfl_xor_sync(0xffffffffu, mx_lo, 2));
        mx_hi = fmaxf(mx_hi, __shfl_xor_sync(0xffffffffu, mx_hi, 1));
        mx_hi = fmaxf(mx_hi, __shfl_xor_sync(0xffffffffu, mx_hi, 2));

        float mn_lo = fmaxf(m_lo, mx_lo), mn_hi = fmaxf(m_hi, mx_hi);
        float al_lo = fexp2(m_lo - mn_lo), al_hi = fexp2(m_hi - mn_hi);
        m_lo = mn_lo; m_hi = mn_hi;

        float rs_lo = 0.0f, rs_hi = 0.0f;
        #pragma unroll
        for (int n = 0; n < 8; ++n) {
            sf[n][0] = fexp2(sf[n][0] - mn_lo);
            sf[n][1] = fexp2(sf[n][1] - mn_lo);
            sf[n][2] = fexp2(sf[n][2] - mn_hi);
            sf[n][3] = fexp2(sf[n][3] - mn_hi);
            rs_lo += sf[n][0] + sf[n][1];
            rs_hi += sf[n][2] + sf[n][3];
        }
        rs_lo += __shfl_xor_sync(0xffffffffu, rs_lo, 1);
        rs_lo += __shfl_xor_sync(0xffffffffu, rs_lo, 2);
        rs_hi += __shfl_xor_sync(0xffffffffu, rs_hi, 1);
        rs_hi += __shfl_xor_sync(0xffffffffu, rs_hi, 2);
        l_lo = l_lo * al_lo + rs_lo;
        l_hi = l_hi * al_hi + rs_hi;

        #pragma unroll
        for (int n = 0; n < 8; ++n) {
            o[n][0] *= al_lo; o[n][1] *= al_lo;
            o[n][2] *= al_hi; o[n][3] *= al_hi;
        }

        // ---- O += P V (P split in registers, V split in smem) ----
        #pragma unroll
        for (int ks = 0; ks < 4; ++ks) {
            uint32_t ph[4], pl[4];
            split2(sf[2*ks][0],   sf[2*ks][1],   ph[0], pl[0]);
            split2(sf[2*ks][2],   sf[2*ks][3],   ph[1], pl[1]);
            split2(sf[2*ks+1][0], sf[2*ks+1][1], ph[2], pl[2]);
            split2(sf[2*ks+1][2], sf[2*ks+1][3], ph[3], pl[3]);
            #pragma unroll
            for (int db = 0; db < 4; ++db) {
                uint32_t vad = stg + 2*FTB + (ks * 16 + lr) * FPB + db * 32 + lc;
                uint32_t vh[4], vl[4];
                ldx4t(vh, vad);
                ldx4t(vl, vad + FTB);
                mma16816(o[2*db],   ph, vh[0], vh[1]);
                mma16816(o[2*db],   ph, vl[0], vl[1]);
                mma16816(o[2*db],   pl, vh[0], vh[1]);
                mma16816(o[2*db+1], ph, vh[2], vh[3]);
                mma16816(o[2*db+1], ph, vl[2], vl[3]);
                mma16816(o[2*db+1], pl, vh[2], vh[3]);
            }
        }

        __syncthreads();
        kv_load(s, (it + 2) * 64);
    }

    // ---- normalize + write split bf16 ctx ----
    const float il = 1.0f / l_lo, ih = 1.0f / l_hi;
    const int gq = q0 + wq0 + rl;
    const size_t row_lo = ((size_t)b * CS + gq) * CD + (size_t)h * CDK + 2 * (lane & 3);
    const size_t row_hi = row_lo + (size_t)8 * CD;
    #pragma unroll
    for (int n = 0; n < 8; ++n) {
        uint32_t hh, ll;
        split2(o[n][0] * il, o[n][1] * il, hh, ll);
        *(uint32_t*)&Chi[row_lo + 8 * n] = hh;
        *(uint32_t*)&Clo[row_lo + 8 * n] = ll;
        split2(o[n][2] * ih, o[n][3] * ih, hh, ll);
        *(uint32_t*)&Chi[row_hi + 8 * n] = hh;
        *(uint32_t*)&Clo[row_hi + 8 * n] = ll;
    }
}

// =====================================================================
// launch
// =====================================================================
extern "C" void kernel_launch(void* const* d_in, const int* in_sizes, int n_in,
                              void* d_out, int out_size) {
    (void)in_sizes; (void)n_in; (void)out_size;
    const float* X   = (const float*)d_in[0];
    const float* bLL = (const float*)d_in[1];
    const float* Wq  = (const float*)d_in[2];
    const float* Wk  = (const float*)d_in[3];
    const float* Wv  = (const float*)d_in[4];
    const float* Wo  = (const float*)d_in[5];
    const float* btr = (const float*)d_in[6];
    float* out = (float*)d_out;

    __nv_bfloat16 *xhi, *xlo, *qkvhi, *qkvlo, *chi, *clo, *wthi, *wtlo;
    cudaGetSymbolAddress((void**)&xhi,   g_xhi);
    cudaGetSymbolAddress((void**)&xlo,   g_xlo);
    cudaGetSymbolAddress((void**)&qkvhi, g_qkvhi);
    cudaGetSymbolAddress((void**)&qkvlo, g_qkvlo);
    cudaGetSymbolAddress((void**)&chi,   g_chi);
    cudaGetSymbolAddress((void**)&clo,   g_clo);
    cudaGetSymbolAddress((void**)&wthi,  g_wthi);
    cudaGetSymbolAddress((void**)&wtlo,  g_wtlo);

    cudaFuncSetAttribute(gemm_mma_kernel<true>,  cudaFuncAttributeMaxDynamicSharedMemorySize, GSMEM);
    cudaFuncSetAttribute(gemm_mma_kernel<false>, cudaFuncAttributeMaxDynamicSharedMemorySize, GSMEM);
    cudaFuncSetAttribute(flasht_kernel, cudaFuncAttributeMaxDynamicSharedMemorySize, FL_SMEM);

    const int n4x = (CM * CD) / 4;
    const dim3 tsg(32, 32), tsb(32, 8);

    // X -> split bf16
    split_kernel<<<(n4x + 255) / 256, 256>>>((const float4*)X,
        (uint32_t*)xhi, (uint32_t*)xlo, n4x);

    // fused weight transpose: Wt rows [0,1024)=Wq^T, [1024,2048)=Wk^T, [2048,3072)=Wv^T
    tsplit_kernel<<<tsg, tsb>>>(Wq, wthi,                          wtlo);
    tsplit_kernel<<<tsg, tsb>>>(Wk, wthi + (size_t)1024 * CD,      wtlo + (size_t)1024 * CD);
    tsplit_kernel<<<tsg, tsb>>>(Wv, wthi + (size_t)2048 * CD,      wtlo + (size_t)2048 * CD);

    // fused QKV projection: [CM, 3072] split bf16 output
    gemm_mma_kernel<true><<<dim3(QP / 256, CM / 128), 256, GSMEM>>>(
        xhi, xlo, wthi, wtlo, nullptr, qkvhi, qkvlo, QP);

    // attention (tensor-core flash) -> split bf16 ctx
    flasht_kernel<<<dim3(CS / 128, CH, CB), 256, FL_SMEM>>>(
        qkvhi, qkvlo, bLL, btr, chi, clo);

    // output projection -> fp32 out
    tsplit_kernel<<<tsg, tsb>>>(Wo, wthi, wtlo);
    gemm_mma_kernel<false><<<dim3(CD / 256, CM / 128), 256, GSMEM>>>(
        chi, clo, wthi, wtlo, out, nullptr, nullptr, CD);
}